// round 2
// baseline (speedup 1.0000x reference)
#include <cuda_runtime.h>
#include <cuda_bf16.h>
#include <math.h>
#include <stdint.h>

#define NB 16
#define NT 2048
#define ND 256
#define NC 128
#define MAXK 20

// ---------- device scratch ----------
__device__ float g_E[NC * NC];        // exp(trans_lp) row-major, diag 0
__device__ float g_winit[NC];         // exp(init_lp)
__device__ float g_dtab[MAXK * NC];   // exp(len_lp[l-1][c])
__device__ float g_miT[ND * NC];      // (means*inv_var) transposed [d][c]
__device__ float g_cb[NC];            // const - 0.5*mq[c]
__device__ float g_iv[ND];            // 1/cov
__device__ float g_f[(size_t)NB * NT * NC]; // exp(emis - rowmax)
__device__ float g_mu[NB * NT];       // rowmax(emis)

// ---------- prep: 1 block x 128 ----------
__global__ void prep_kernel(const float* __restrict__ means,
                            const float* __restrict__ cov,
                            const float* __restrict__ trans,
                            const float* __restrict__ initlg,
                            const float* __restrict__ lograte) {
    const int c = threadIdx.x;
    __shared__ float sh[NC];
    __shared__ float shc;

    float lsum = 0.f;
    for (int d = c; d < ND; d += NC) { float cv = cov[d]; g_iv[d] = 1.0f / cv; lsum += logf(cv); }
    sh[c] = lsum;
    __syncthreads();
    if (c == 0) {
        float tot = 0.f;
        for (int i = 0; i < NC; ++i) tot += sh[i];
        shc = -0.5f * (256.0f * 1.8378770664093453f + tot);
    }
    __syncthreads();
    const float cst = shc;

    float mq = 0.f;
    for (int d = 0; d < ND; ++d) {
        float m = means[c * ND + d];
        float mi = m * g_iv[d];
        g_miT[d * NC + c] = mi;
        mq = fmaf(mi, m, mq);
    }
    g_cb[c] = cst - 0.5f * mq;

    // E column c: softmax over rows of masked logits
    float mx = -3.0e38f;
    for (int i = 0; i < NC; ++i) {
        float v = (i == c) ? -1.0e9f : trans[i * NC + c];
        mx = fmaxf(mx, v);
    }
    float ssum = 0.f;
    for (int i = 0; i < NC; ++i) {
        float v = (i == c) ? -1.0e9f : trans[i * NC + c];
        ssum += expf(v - mx);
    }
    float inv = 1.0f / ssum;
    for (int i = 0; i < NC; ++i)
        g_E[i * NC + c] = (i == c) ? 0.0f : expf(trans[i * NC + c] - mx) * inv;

    __syncthreads();
    sh[c] = initlg[c];
    __syncthreads();
    float m2 = sh[0];
    for (int i = 1; i < NC; ++i) m2 = fmaxf(m2, sh[i]);
    float s2 = 0.f;
    for (int i = 0; i < NC; ++i) s2 += expf(sh[i] - m2);
    g_winit[c] = expf(initlg[c] - m2) / s2;

    float r = lograte[c];
    float lam = expf(r);
    float lg = 0.f;
    for (int l = 1; l <= MAXK; ++l) {
        lg += logf((float)l);
        g_dtab[(l - 1) * NC + c] = expf(fmaf((float)l, r, -lam) - lg);
    }
}

// ---------- emission GEMM + exp epilogue: 512 blocks x 256 ----------
__global__ __launch_bounds__(256) void emis_kernel(const float* __restrict__ feat) {
    __shared__ float A[64][64];     // rows x k-chunk
    __shared__ float Bt[32][NC];
    __shared__ float ivs[32];

    const int tid = threadIdx.x;
    const int r0 = blockIdx.x * 64;
    const int cg = tid & 15;        // 16 col groups of 8
    const int rr = tid >> 4;        // base row (0..15), rows rr+16i

    float acc[4][8];
    float xq[4] = {0.f, 0.f, 0.f, 0.f};
#pragma unroll
    for (int i = 0; i < 4; ++i)
#pragma unroll
        for (int k = 0; k < 8; ++k) acc[i][k] = 0.f;

    for (int d0 = 0; d0 < ND; d0 += 32) {
        __syncthreads();
        // A tile 64x32 = 512 float4
#pragma unroll
        for (int k = 0; k < 2; ++k) {
            int i = tid + k * 256;
            int row = i >> 3, q = i & 7;
            *(float4*)&A[row][q * 4] = *(const float4*)&feat[(size_t)(r0 + row) * ND + d0 + q * 4];
        }
        // Bt tile 32x128 = 1024 float4
#pragma unroll
        for (int k = 0; k < 4; ++k) {
            int i = tid + k * 256;
            int drow = i >> 5, q = i & 31;
            *(float4*)&Bt[drow][q * 4] = *(const float4*)&g_miT[(size_t)(d0 + drow) * NC + q * 4];
        }
        if (tid < 32) ivs[tid] = g_iv[d0 + tid];
        __syncthreads();

#pragma unroll 4
        for (int dd = 0; dd < 32; ++dd) {
            float iv = ivs[dd];
            float a0 = A[rr][dd], a1 = A[rr + 16][dd], a2 = A[rr + 32][dd], a3 = A[rr + 48][dd];
            xq[0] = fmaf(a0 * iv, a0, xq[0]);
            xq[1] = fmaf(a1 * iv, a1, xq[1]);
            xq[2] = fmaf(a2 * iv, a2, xq[2]);
            xq[3] = fmaf(a3 * iv, a3, xq[3]);
            float4 b0 = *(const float4*)&Bt[dd][cg * 8];
            float4 b1 = *(const float4*)&Bt[dd][cg * 8 + 4];
            float bb[8] = {b0.x, b0.y, b0.z, b0.w, b1.x, b1.y, b1.z, b1.w};
            float aa[4] = {a0, a1, a2, a3};
#pragma unroll
            for (int i = 0; i < 4; ++i)
#pragma unroll
                for (int k = 0; k < 8; ++k) acc[i][k] = fmaf(aa[i], bb[k], acc[i][k]);
        }
    }

    float4 cb0 = *(const float4*)&g_cb[cg * 8];
    float4 cb1 = *(const float4*)&g_cb[cg * 8 + 4];
    float cb[8] = {cb0.x, cb0.y, cb0.z, cb0.w, cb1.x, cb1.y, cb1.z, cb1.w};
    const float L2E = 1.4426950408889634f;

#pragma unroll
    for (int i = 0; i < 4; ++i) {
        float hq = -0.5f * xq[i];
        float e[8], m = -3.0e38f;
#pragma unroll
        for (int k = 0; k < 8; ++k) { e[k] = acc[i][k] + hq + cb[k]; m = fmaxf(m, e[k]); }
#pragma unroll
        for (int off = 8; off >= 1; off >>= 1)
            m = fmaxf(m, __shfl_xor_sync(0xffffffffu, m, off, 16));
        float4 o0, o1;
        o0.x = exp2f((e[0] - m) * L2E); o0.y = exp2f((e[1] - m) * L2E);
        o0.z = exp2f((e[2] - m) * L2E); o0.w = exp2f((e[3] - m) * L2E);
        o1.x = exp2f((e[4] - m) * L2E); o1.y = exp2f((e[5] - m) * L2E);
        o1.z = exp2f((e[6] - m) * L2E); o1.w = exp2f((e[7] - m) * L2E);
        size_t row = (size_t)(r0 + rr + 16 * i);
        *(float4*)&g_f[row * NC + cg * 8] = o0;
        *(float4*)&g_f[row * NC + cg * 8 + 4] = o1;
        if (cg == 0) g_mu[row] = m;
    }
}

// ---------- recursion: 16 blocks x 256 ----------
__global__ __launch_bounds__(256, 1) void rec_kernel(const int* __restrict__ lengths,
                                                     float* __restrict__ out) {
    const int b = blockIdx.x, tid = threadIdx.x;
    const int c = tid >> 1, h = tid & 1, wp = tid >> 5, lane = tid & 31;
    __shared__ __align__(16) float psh[264]; // copy1 at 0, copy2 at 132
    __shared__ float shm[8], shs[8];

    float Er[64];
#pragma unroll
    for (int k = 0; k < 16; ++k)
        *(float4*)&Er[k * 4] = *(const float4*)&g_E[c * NC + h * 64 + k * 4];
    float Dr[MAXK];
#pragma unroll
    for (int j = 0; j < MAXK; ++j) Dr[j] = g_dtab[j * NC + c];
    float v[MAXK];
#pragma unroll
    for (int j = 0; j < MAXK; ++j) v[j] = 0.f;

    const int len = lengths[b];
    const float* fp = g_f + (size_t)b * NT * NC;
    float wv = g_winit[c];
    float f_cur = __ldg(&fp[c]);
    float rm = 1.0f, sigma = 0.f, mu_cur = 0.f;
    if (tid == 0) mu_cur = __ldg(&g_mu[b * NT]);

    for (int t = 1;; ++t) {
        // window shift + multiply by F_{t-1}
        float gh = f_cur * rm;
#pragma unroll
        for (int j = MAXK - 1; j >= 1; --j) v[j] = v[j - 1] * gh;
        v[0] = wv * f_cur;
        float al = 0.f;
#pragma unroll
        for (int j = 0; j < MAXK; ++j) al = fmaf(v[j], Dr[j], al);

        int tn = (t < NT) ? t : (NT - 1);
        float f_nxt = __ldg(&fp[(size_t)tn * NC + c]);
        float mu_nxt = 0.f;
        if (tid == 0) { sigma += mu_cur; mu_nxt = __ldg(&g_mu[b * NT + tn]); }

        // block max of alpha
        float mx = al;
#pragma unroll
        for (int o = 16; o >= 1; o >>= 1)
            mx = fmaxf(mx, __shfl_xor_sync(0xffffffffu, mx, o));
        if (lane == 0) shm[wp] = mx;
        __syncthreads();
        float m = shm[0];
#pragma unroll
        for (int i = 1; i < 8; ++i) m = fmaxf(m, shm[i]);

        if (t == len) {
            float s = h ? 0.f : al;
#pragma unroll
            for (int o = 16; o >= 1; o >>= 1)
                s += __shfl_xor_sync(0xffffffffu, s, o);
            if (lane == 0) shs[wp] = s;
            __syncthreads();
            if (tid == 0) {
                float st = 0.f;
                for (int i = 0; i < 8; ++i) st += shs[i];
                out[b] = sigma + logf(st);
            }
            break;
        }

        rm = __fdividef(1.0f, m);
        float p = al * rm;
        if (h == 0) psh[c] = p; else psh[132 + c] = p;
        __syncthreads();

        // matvec half-row: w[c] partial
        const float* pb = h ? &psh[132 + 64] : &psh[0];
        float a0 = 0.f, a1 = 0.f, a2 = 0.f, a3 = 0.f;
#pragma unroll
        for (int k = 0; k < 16; ++k) {
            float4 pv = *(const float4*)&pb[k * 4];
            a0 = fmaf(Er[k * 4 + 0], pv.x, a0);
            a1 = fmaf(Er[k * 4 + 1], pv.y, a1);
            a2 = fmaf(Er[k * 4 + 2], pv.z, a2);
            a3 = fmaf(Er[k * 4 + 3], pv.w, a3);
        }
        float wacc = (a0 + a1) + (a2 + a3);
        wv = wacc + __shfl_xor_sync(0xffffffffu, wacc, 1);
        if (tid == 0) sigma += logf(m);
        f_cur = f_nxt; mu_cur = mu_nxt;
    }
}

extern "C" void kernel_launch(void* const* d_in, const int* in_sizes, int n_in,
                              void* d_out, int out_size) {
    const float* feat    = (const float*)d_in[0];
    const int*   lengths = (const int*)d_in[1];
    const float* means   = (const float*)d_in[2];
    const float* cov     = (const float*)d_in[3];
    const float* trans   = (const float*)d_in[4];
    const float* initlg  = (const float*)d_in[5];
    const float* lograte = (const float*)d_in[6];
    float* out = (float*)d_out;

    prep_kernel<<<1, 128>>>(means, cov, trans, initlg, lograte);
    emis_kernel<<<512, 256>>>(feat);
    rec_kernel<<<NB, 256>>>(lengths, out);
}

// round 3
// speedup vs baseline: 1.5700x; 1.5700x over previous
#include <cuda_runtime.h>
#include <cuda_bf16.h>
#include <math.h>
#include <stdint.h>

#define NB 16
#define NT 2048
#define ND 256
#define NC 128
#define MAXK 20

typedef unsigned long long ull;

union U2 { float4 f4; ull u[2]; };

#define FMA2(acc, a, b) asm("fma.rn.f32x2 %0, %1, %2, %0;" : "+l"(acc) : "l"(a), "l"(b))
#define PACK2(d, x, y)  asm("mov.b64 %0, {%1, %2};" : "=l"(d) : "f"(x), "f"(y))
#define UNPACK2(x, y, d) asm("mov.b64 {%0, %1}, %2;" : "=f"(x), "=f"(y) : "l"(d))

// ---------- device scratch ----------
__device__ float g_E[NC * NC];        // exp(trans_lp) row-major, diag 0
__device__ float g_winit[NC];         // exp(init_lp)
__device__ float g_dtab[MAXK * NC];   // exp(len_lp[l-1][c])
__device__ float g_miT[ND * NC];      // (means*inv_var)^T  [d][c]
__device__ float g_cb[NC];            // const - 0.5*mq[c]
__device__ float g_iv[ND];            // 1/cov
__device__ float g_f[(size_t)NB * NT * NC]; // exp(emis - rowmax)
__device__ float g_mu[NB * NT];       // rowmax(emis)

// ---------- prep: 129 blocks x 128 ----------
__global__ void prep_kernel(const float* __restrict__ means,
                            const float* __restrict__ cov,
                            const float* __restrict__ trans,
                            const float* __restrict__ initlg,
                            const float* __restrict__ lograte) {
    const int c = threadIdx.x;
    const int lane = c & 31, wid = c >> 5;

    if (blockIdx.x < NC) {
        // E column col: softmax over rows of masked logits
        const int col = blockIdx.x;
        __shared__ float red[4];
        float v = (c == col) ? -1.0e9f : trans[c * NC + col];
        float mx = v;
#pragma unroll
        for (int o = 16; o >= 1; o >>= 1)
            mx = fmaxf(mx, __shfl_xor_sync(0xffffffffu, mx, o));
        if (lane == 0) red[wid] = mx;
        __syncthreads();
        mx = fmaxf(fmaxf(red[0], red[1]), fmaxf(red[2], red[3]));
        __syncthreads();
        float ex = (c == col) ? 0.0f : expf(v - mx);
        float s = ex;
#pragma unroll
        for (int o = 16; o >= 1; o >>= 1)
            s += __shfl_xor_sync(0xffffffffu, s, o);
        if (lane == 0) red[wid] = s;
        __syncthreads();
        float tot = red[0] + red[1] + red[2] + red[3];
        g_E[c * NC + col] = ex / tot;
        return;
    }

    // block NC: everything else
    __shared__ float sh[NC];
    __shared__ float shc;

    float lsum = 0.f;
    for (int d = c; d < ND; d += NC) { float cv = cov[d]; g_iv[d] = 1.0f / cv; lsum += logf(cv); }
    sh[c] = lsum;
    __syncthreads();
    if (c == 0) {
        float tot = 0.f;
        for (int i = 0; i < NC; ++i) tot += sh[i];
        shc = -0.5f * (256.0f * 1.8378770664093453f + tot);
    }
    __syncthreads();
    const float cst = shc;

    float mq = 0.f;
    for (int d = 0; d < ND; ++d) {
        float m = means[c * ND + d];
        float mi = m * g_iv[d];
        g_miT[d * NC + c] = mi;
        mq = fmaf(mi, m, mq);
    }
    g_cb[c] = cst - 0.5f * mq;

    __syncthreads();
    sh[c] = initlg[c];
    __syncthreads();
    float m2 = sh[0];
    for (int i = 1; i < NC; ++i) m2 = fmaxf(m2, sh[i]);
    float s2 = 0.f;
    for (int i = 0; i < NC; ++i) s2 += expf(sh[i] - m2);
    g_winit[c] = expf(initlg[c] - m2) / s2;

    float r = lograte[c];
    float lam = expf(r);
    float lg = 0.f;
    for (int l = 1; l <= MAXK; ++l) {
        lg += logf((float)l);
        g_dtab[(l - 1) * NC + c] = expf(fmaf((float)l, r, -lam) - lg);
    }
}

// ---------- emission GEMM + exp epilogue: 512 blocks x 256 ----------
__global__ __launch_bounds__(256) void emis_kernel(const float* __restrict__ feat) {
    __shared__ float A[64][68];     // 64 rows x 32 k, padded
    __shared__ float Bt[32][132];   // 32 k x 128 c, padded
    __shared__ float ivs[32];

    const int tid = threadIdx.x;
    const int r0 = blockIdx.x * 64;
    const int cg = tid & 15;        // col group: cols cg*4..+3 and 64+cg*4..+3
    const int rr = tid >> 4;        // base row; rows rr + 16*i

    ull acc2[4][4];                 // [row i][pair k]; pairs: cols (4cg..)+2k halves
#pragma unroll
    for (int i = 0; i < 4; ++i)
#pragma unroll
        for (int k = 0; k < 4; ++k) acc2[i][k] = 0ull;
    float xq[4] = {0.f, 0.f, 0.f, 0.f};

    for (int d0 = 0; d0 < ND; d0 += 32) {
        __syncthreads();
        // A tile 64x32 = 512 float4
#pragma unroll
        for (int k = 0; k < 2; ++k) {
            int i = tid + k * 256;
            int row = i >> 3, q = i & 7;
            *(float4*)&A[row][q * 4] = *(const float4*)&feat[(size_t)(r0 + row) * ND + d0 + q * 4];
        }
        // Bt tile 32x128 = 1024 float4
#pragma unroll
        for (int k = 0; k < 4; ++k) {
            int i = tid + k * 256;
            int drow = i >> 5, q = i & 31;
            *(float4*)&Bt[drow][q * 4] = *(const float4*)&g_miT[(size_t)(d0 + drow) * NC + q * 4];
        }
        if (tid < 32) ivs[tid] = g_iv[d0 + tid];
        __syncthreads();

        // xq partials: each lane covers dd = cg, cg+16 (dedup across the 16-group)
#pragma unroll
        for (int u = 0; u < 2; ++u) {
            int dd = cg + u * 16;
            float iv = ivs[dd];
            float a0 = A[rr][dd], a1 = A[rr + 16][dd], a2 = A[rr + 32][dd], a3 = A[rr + 48][dd];
            xq[0] = fmaf(a0 * iv, a0, xq[0]);
            xq[1] = fmaf(a1 * iv, a1, xq[1]);
            xq[2] = fmaf(a2 * iv, a2, xq[2]);
            xq[3] = fmaf(a3 * iv, a3, xq[3]);
        }

#pragma unroll 8
        for (int dd = 0; dd < 32; ++dd) {
            U2 b0, b1;
            b0.f4 = *(const float4*)&Bt[dd][cg * 4];
            b1.f4 = *(const float4*)&Bt[dd][64 + cg * 4];
            float a0 = A[rr][dd], a1 = A[rr + 16][dd], a2 = A[rr + 32][dd], a3 = A[rr + 48][dd];
            ull aa;
            PACK2(aa, a0, a0);
            FMA2(acc2[0][0], aa, b0.u[0]); FMA2(acc2[0][1], aa, b0.u[1]);
            FMA2(acc2[0][2], aa, b1.u[0]); FMA2(acc2[0][3], aa, b1.u[1]);
            PACK2(aa, a1, a1);
            FMA2(acc2[1][0], aa, b0.u[0]); FMA2(acc2[1][1], aa, b0.u[1]);
            FMA2(acc2[1][2], aa, b1.u[0]); FMA2(acc2[1][3], aa, b1.u[1]);
            PACK2(aa, a2, a2);
            FMA2(acc2[2][0], aa, b0.u[0]); FMA2(acc2[2][1], aa, b0.u[1]);
            FMA2(acc2[2][2], aa, b1.u[0]); FMA2(acc2[2][3], aa, b1.u[1]);
            PACK2(aa, a3, a3);
            FMA2(acc2[3][0], aa, b0.u[0]); FMA2(acc2[3][1], aa, b0.u[1]);
            FMA2(acc2[3][2], aa, b1.u[0]); FMA2(acc2[3][3], aa, b1.u[1]);
        }
    }

    // complete xq across the 16-lane group
#pragma unroll
    for (int o = 1; o < 16; o <<= 1) {
#pragma unroll
        for (int i = 0; i < 4; ++i)
            xq[i] += __shfl_xor_sync(0xffffffffu, xq[i], o, 16);
    }

    float cb[8];
    {
        float4 cb0 = *(const float4*)&g_cb[cg * 4];
        float4 cb1 = *(const float4*)&g_cb[64 + cg * 4];
        cb[0] = cb0.x; cb[1] = cb0.y; cb[2] = cb0.z; cb[3] = cb0.w;
        cb[4] = cb1.x; cb[5] = cb1.y; cb[6] = cb1.z; cb[7] = cb1.w;
    }
    const float L2E = 1.4426950408889634f;

#pragma unroll
    for (int i = 0; i < 4; ++i) {
        float hq = -0.5f * xq[i];
        float e[8], m = -3.0e38f;
#pragma unroll
        for (int k = 0; k < 4; ++k) {
            float lo, hi;
            UNPACK2(lo, hi, acc2[i][k]);
            e[k * 2] = lo + hq + cb[k * 2];
            e[k * 2 + 1] = hi + hq + cb[k * 2 + 1];
        }
#pragma unroll
        for (int k = 0; k < 8; ++k) m = fmaxf(m, e[k]);
#pragma unroll
        for (int off = 8; off >= 1; off >>= 1)
            m = fmaxf(m, __shfl_xor_sync(0xffffffffu, m, off, 16));
        float4 o0, o1;
        o0.x = exp2f((e[0] - m) * L2E); o0.y = exp2f((e[1] - m) * L2E);
        o0.z = exp2f((e[2] - m) * L2E); o0.w = exp2f((e[3] - m) * L2E);
        o1.x = exp2f((e[4] - m) * L2E); o1.y = exp2f((e[5] - m) * L2E);
        o1.z = exp2f((e[6] - m) * L2E); o1.w = exp2f((e[7] - m) * L2E);
        size_t row = (size_t)(r0 + rr + 16 * i);
        *(float4*)&g_f[row * NC + cg * 4] = o0;
        *(float4*)&g_f[row * NC + 64 + cg * 4] = o1;
        if (cg == 0) g_mu[row] = m;
    }
}

// ---------- recursion: 16 blocks x 256, 1 sync/step ----------
__global__ __launch_bounds__(256, 1) void rec_kernel(const int* __restrict__ lengths,
                                                     float* __restrict__ out) {
    const int b = blockIdx.x, tid = threadIdx.x;
    const int c = tid >> 1, h = tid & 1, wp = tid >> 5, lane = tid & 31;
    __shared__ __align__(16) float psh[2][264];
    __shared__ __align__(16) float shm[2][8];
    __shared__ float shs[8];

    // E half-row, packed pairs (64 floats -> 32 ull)
    ull Er2[32];
#pragma unroll
    for (int k = 0; k < 16; ++k) {
        U2 u;
        u.f4 = *(const float4*)&g_E[c * NC + h * 64 + k * 4];
        Er2[k * 2] = u.u[0];
        Er2[k * 2 + 1] = u.u[1];
    }
    float Dr[MAXK];
#pragma unroll
    for (int j = 0; j < MAXK; ++j) Dr[j] = g_dtab[j * NC + c];
    float v[MAXK];
#pragma unroll
    for (int j = 0; j < MAXK; ++j) v[j] = 0.f;

    const int len = lengths[b];
    const float* fp = g_f + (size_t)b * NT * NC;
    float wv = g_winit[c];
    float f_cur = __ldg(&fp[c]);
    float mu_cur = __ldg(&g_mu[b * NT]);
    float rm = 1.0f, lgm = 0.0f, sigma = 0.0f;

    for (int t = 1;; ++t) {
        const int par = t & 1;
        // window: divide state by m_{t-1} (folded) and advance by F_{t-1}
        float fr = f_cur * rm;
#pragma unroll
        for (int j = MAXK - 1; j >= 1; --j) v[j] = v[j - 1] * fr;
        v[0] = wv * fr;
        float al0 = 0.f, al1 = 0.f, al2 = 0.f, al3 = 0.f;
#pragma unroll
        for (int j = 0; j < MAXK; j += 4) {
            al0 = fmaf(v[j], Dr[j], al0);
            al1 = fmaf(v[j + 1], Dr[j + 1], al1);
            al2 = fmaf(v[j + 2], Dr[j + 2], al2);
            al3 = fmaf(v[j + 3], Dr[j + 3], al3);
        }
        float al = (al0 + al1) + (al2 + al3);

        sigma += mu_cur + lgm;  // uniform across threads

        int tn = (t < NT) ? t : (NT - 1);
        float f_nxt = __ldg(&fp[(size_t)tn * NC + c]);
        float mu_nxt = __ldg(&g_mu[b * NT + tn]);

        if (t == len) {
            float s = h ? 0.f : al;
#pragma unroll
            for (int o = 16; o >= 1; o >>= 1)
                s += __shfl_xor_sync(0xffffffffu, s, o);
            if (lane == 0) shs[wp] = s;
            __syncthreads();
            if (tid == 0) {
                float st = 0.f;
                for (int i = 0; i < 8; ++i) st += shs[i];
                out[b] = sigma + logf(st);
            }
            break;
        }

        // next-step normalizer (off critical path) + publish alpha
        float mx = al;
#pragma unroll
        for (int o = 16; o >= 1; o >>= 1)
            mx = fmaxf(mx, __shfl_xor_sync(0xffffffffu, mx, o));
        if (lane == 0) shm[par][wp] = mx;
        psh[par][h ? 132 + c : c] = al;
        __syncthreads();

        float4 ma = *(const float4*)&shm[par][0];
        float4 mb = *(const float4*)&shm[par][4];
        float m = fmaxf(fmaxf(fmaxf(ma.x, ma.y), fmaxf(ma.z, ma.w)),
                        fmaxf(fmaxf(mb.x, mb.y), fmaxf(mb.z, mb.w)));
        rm = __fdividef(1.0f, m);
        lgm = __logf(m);

        // matvec half-row on unnormalized alpha
        const float* pb = h ? &psh[par][132 + 64] : &psh[par][0];
        ull acc0 = 0ull, acc1 = 0ull, acc2 = 0ull, acc3 = 0ull;
#pragma unroll
        for (int k = 0; k < 16; k += 2) {
            U2 p0, p1;
            p0.f4 = *(const float4*)&pb[k * 4];
            p1.f4 = *(const float4*)&pb[k * 4 + 4];
            FMA2(acc0, Er2[k * 2], p0.u[0]);
            FMA2(acc1, Er2[k * 2 + 1], p0.u[1]);
            FMA2(acc2, Er2[k * 2 + 2], p1.u[0]);
            FMA2(acc3, Er2[k * 2 + 3], p1.u[1]);
        }
        float x0, y0, x1, y1, x2, y2, x3, y3;
        UNPACK2(x0, y0, acc0); UNPACK2(x1, y1, acc1);
        UNPACK2(x2, y2, acc2); UNPACK2(x3, y3, acc3);
        float wacc = ((x0 + y0) + (x1 + y1)) + ((x2 + y2) + (x3 + y3));
        wv = wacc + __shfl_xor_sync(0xffffffffu, wacc, 1);

        f_cur = f_nxt;
        mu_cur = mu_nxt;
    }
}

extern "C" void kernel_launch(void* const* d_in, const int* in_sizes, int n_in,
                              void* d_out, int out_size) {
    const float* feat    = (const float*)d_in[0];
    const int*   lengths = (const int*)d_in[1];
    const float* means   = (const float*)d_in[2];
    const float* cov     = (const float*)d_in[3];
    const float* trans   = (const float*)d_in[4];
    const float* initlg  = (const float*)d_in[5];
    const float* lograte = (const float*)d_in[6];
    float* out = (float*)d_out;

    prep_kernel<<<NC + 1, 128>>>(means, cov, trans, initlg, lograte);
    emis_kernel<<<512, 256>>>(feat);
    rec_kernel<<<NB, 256>>>(lengths, out);
}

// round 5
// speedup vs baseline: 1.7382x; 1.1071x over previous
#include <cuda_runtime.h>
#include <cuda_bf16.h>
#include <math.h>
#include <stdint.h>

#define NB 16
#define NT 2048
#define ND 256
#define NC 128
#define MAXK 20

typedef unsigned long long ull;

union U2 { float4 f4; ull u[2]; };

#define FMA2(acc, a, b) asm("fma.rn.f32x2 %0, %1, %2, %0;" : "+l"(acc) : "l"(a), "l"(b))
#define PACK2(d, x, y)  asm("mov.b64 %0, {%1, %2};" : "=l"(d) : "f"(x), "f"(y))
#define UNPACK2(x, y, d) asm("mov.b64 {%0, %1}, %2;" : "=f"(x), "=f"(y) : "l"(d))

// ---------- device scratch ----------
__device__ float g_E[NC * NC];        // exp(trans_lp) row-major, diag 0
__device__ float g_winit[NC];         // exp(init_lp)
__device__ float g_dtab[MAXK * NC];   // exp(len_lp[l-1][c])
__device__ float g_miT[ND * NC];      // (means*inv_var)^T  [d][c]
__device__ float g_cb[NC];            // const - 0.5*mq[c]
__device__ float g_iv[ND];            // 1/cov
__device__ float g_f[(size_t)NB * NT * NC]; // exp(emis - rowmax)
__device__ float g_mu[NB * NT];       // rowmax(emis)

// ---------- prep: 129 blocks x 128 ----------
__global__ void prep_kernel(const float* __restrict__ means,
                            const float* __restrict__ cov,
                            const float* __restrict__ trans,
                            const float* __restrict__ initlg,
                            const float* __restrict__ lograte) {
    const int c = threadIdx.x;
    const int lane = c & 31, wid = c >> 5;

    if (blockIdx.x < NC) {
        const int col = blockIdx.x;
        // miT rows d = col, col+128 (+ g_iv)
#pragma unroll
        for (int u = 0; u < 2; ++u) {
            int d = col + u * 128;
            float iv = 1.0f / cov[d];
            if (c == 0) g_iv[d] = iv;
            g_miT[d * NC + c] = means[c * ND + d] * iv;
        }
        // E column col: softmax over rows of masked logits
        __shared__ float red[4];
        float v = (c == col) ? -1.0e9f : trans[c * NC + col];
        float mx = v;
#pragma unroll
        for (int o = 16; o >= 1; o >>= 1)
            mx = fmaxf(mx, __shfl_xor_sync(0xffffffffu, mx, o));
        if (lane == 0) red[wid] = mx;
        __syncthreads();
        mx = fmaxf(fmaxf(red[0], red[1]), fmaxf(red[2], red[3]));
        __syncthreads();
        float ex = (c == col) ? 0.0f : expf(v - mx);
        float s = ex;
#pragma unroll
        for (int o = 16; o >= 1; o >>= 1)
            s += __shfl_xor_sync(0xffffffffu, s, o);
        if (lane == 0) red[wid] = s;
        __syncthreads();
        float tot = red[0] + red[1] + red[2] + red[3];
        g_E[c * NC + col] = ex / tot;
        return;
    }

    // block NC: cb, winit, dtab
    __shared__ float sh[NC];
    __shared__ float shc;

    float lsum = 0.f;
    for (int d = c; d < ND; d += NC) lsum += logf(cov[d]);
    sh[c] = lsum;
    __syncthreads();
    if (c == 0) {
        float tot = 0.f;
        for (int i = 0; i < NC; ++i) tot += sh[i];
        shc = -0.5f * (256.0f * 1.8378770664093453f + tot);
    }
    __syncthreads();
    const float cst = shc;

    float mq = 0.f;
#pragma unroll 8
    for (int d = 0; d < ND; ++d) {
        float m = means[c * ND + d];
        mq = fmaf(m * m, 1.0f / cov[d], mq);
    }
    g_cb[c] = cst - 0.5f * mq;

    __syncthreads();
    sh[c] = initlg[c];
    __syncthreads();
    float m2 = sh[0];
    for (int i = 1; i < NC; ++i) m2 = fmaxf(m2, sh[i]);
    float s2 = 0.f;
    for (int i = 0; i < NC; ++i) s2 += expf(sh[i] - m2);
    g_winit[c] = expf(initlg[c] - m2) / s2;

    float r = lograte[c];
    float lam = expf(r);
    float lg = 0.f;
    for (int l = 1; l <= MAXK; ++l) {
        lg += logf((float)l);
        g_dtab[(l - 1) * NC + c] = expf(fmaf((float)l, r, -lam) - lg);
    }
}

// ---------- emission GEMM + exp epilogue: 256 blocks x 256 ----------
__global__ __launch_bounds__(256) void emis_kernel(const float* __restrict__ feat) {
    __shared__ float A[128][40];    // 128 rows x 32 k, stride 40 (16B aligned)
    __shared__ float Bt[32][132];   // 32 k x 128 c, stride 132 (16B aligned)
    __shared__ float ivs[32];

    const int tid = threadIdx.x;
    const int r0 = blockIdx.x * 128;
    const int cg = tid & 15;        // col group: cols cg*4..+3 and 64+cg*4..+3
    const int rr = tid >> 4;        // base row; rows rr + 16*i, i<8

    ull acc2[8][4];
#pragma unroll
    for (int i = 0; i < 8; ++i)
#pragma unroll
        for (int k = 0; k < 4; ++k) acc2[i][k] = 0ull;
    float xq[8];
#pragma unroll
    for (int i = 0; i < 8; ++i) xq[i] = 0.f;

    for (int d0 = 0; d0 < ND; d0 += 32) {
        __syncthreads();
        // A tile 128x32 = 1024 float4
#pragma unroll
        for (int k = 0; k < 4; ++k) {
            int i = tid + k * 256;
            int row = i >> 3, q = i & 7;
            *(float4*)&A[row][q * 4] = *(const float4*)&feat[(size_t)(r0 + row) * ND + d0 + q * 4];
        }
        // Bt tile 32x128 = 1024 float4
#pragma unroll
        for (int k = 0; k < 4; ++k) {
            int i = tid + k * 256;
            int drow = i >> 5, q = i & 31;
            *(float4*)&Bt[drow][q * 4] = *(const float4*)&g_miT[(size_t)(d0 + drow) * NC + q * 4];
        }
        if (tid < 32) ivs[tid] = g_iv[d0 + tid];
        __syncthreads();

        // xq partials: each lane covers dd = cg, cg+16 (dedup across 16-group)
#pragma unroll
        for (int u = 0; u < 2; ++u) {
            int dd = cg + u * 16;
            float iv = ivs[dd];
#pragma unroll
            for (int i = 0; i < 8; ++i) {
                float a = A[rr + 16 * i][dd];
                xq[i] = fmaf(a * iv, a, xq[i]);
            }
        }

#pragma unroll 8
        for (int dd = 0; dd < 32; ++dd) {
            U2 b0, b1;
            b0.f4 = *(const float4*)&Bt[dd][cg * 4];
            b1.f4 = *(const float4*)&Bt[dd][64 + cg * 4];
#pragma unroll
            for (int i = 0; i < 8; ++i) {
                float a = A[rr + 16 * i][dd];
                ull aa;
                PACK2(aa, a, a);
                FMA2(acc2[i][0], aa, b0.u[0]);
                FMA2(acc2[i][1], aa, b0.u[1]);
                FMA2(acc2[i][2], aa, b1.u[0]);
                FMA2(acc2[i][3], aa, b1.u[1]);
            }
        }
    }

    // complete xq across 16-lane group
#pragma unroll
    for (int o = 1; o < 16; o <<= 1) {
#pragma unroll
        for (int i = 0; i < 8; ++i)
            xq[i] += __shfl_xor_sync(0xffffffffu, xq[i], o, 16);
    }

    float cb[8];
    {
        float4 cb0 = *(const float4*)&g_cb[cg * 4];
        float4 cb1 = *(const float4*)&g_cb[64 + cg * 4];
        cb[0] = cb0.x; cb[1] = cb0.y; cb[2] = cb0.z; cb[3] = cb0.w;
        cb[4] = cb1.x; cb[5] = cb1.y; cb[6] = cb1.z; cb[7] = cb1.w;
    }
    const float L2E = 1.4426950408889634f;

#pragma unroll
    for (int i = 0; i < 8; ++i) {
        float hq = -0.5f * xq[i];
        float e[8], m = -3.0e38f;
#pragma unroll
        for (int k = 0; k < 4; ++k) {
            float lo, hi;
            UNPACK2(lo, hi, acc2[i][k]);
            e[k * 2] = lo + hq + cb[k * 2];
            e[k * 2 + 1] = hi + hq + cb[k * 2 + 1];
        }
#pragma unroll
        for (int k = 0; k < 8; ++k) m = fmaxf(m, e[k]);
#pragma unroll
        for (int off = 8; off >= 1; off >>= 1)
            m = fmaxf(m, __shfl_xor_sync(0xffffffffu, m, off, 16));
        float4 o0, o1;
        o0.x = exp2f((e[0] - m) * L2E); o0.y = exp2f((e[1] - m) * L2E);
        o0.z = exp2f((e[2] - m) * L2E); o0.w = exp2f((e[3] - m) * L2E);
        o1.x = exp2f((e[4] - m) * L2E); o1.y = exp2f((e[5] - m) * L2E);
        o1.z = exp2f((e[6] - m) * L2E); o1.w = exp2f((e[7] - m) * L2E);
        size_t row = (size_t)(r0 + rr + 16 * i);
        *(float4*)&g_f[row * NC + cg * 4] = o0;
        *(float4*)&g_f[row * NC + 64 + cg * 4] = o1;
        if (cg == 0) g_mu[row] = m;
    }
}

// ---------- recursion: 16 blocks x 128 (1 thread = 1 channel) ----------
__global__ __launch_bounds__(128, 1) void rec_kernel(const int* __restrict__ lengths,
                                                     float* __restrict__ out) {
    const int b = blockIdx.x, c = threadIdx.x;
    const int w = c >> 5, lane = c & 31;
    __shared__ __align__(16) float psh[2][NC];
    __shared__ __align__(16) float shm[2][4];
    __shared__ float shs[4];

    // full E row, packed pairs (128 floats -> 64 ull)
    ull Er2[64];
#pragma unroll
    for (int k = 0; k < 32; ++k) {
        U2 u;
        u.f4 = *(const float4*)&g_E[c * NC + k * 4];
        Er2[k * 2] = u.u[0];
        Er2[k * 2 + 1] = u.u[1];
    }
    float Dr[MAXK];
#pragma unroll
    for (int j = 0; j < MAXK; ++j) Dr[j] = g_dtab[j * NC + c];
    float v[MAXK];
#pragma unroll
    for (int j = 0; j < MAXK; ++j) v[j] = 0.f;

    const int len = lengths[b];
    const float* fp = g_f + (size_t)b * NT * NC;
    float wv = g_winit[c];
    float f_cur = __ldg(&fp[c]);
    float mu_cur = __ldg(&g_mu[b * NT]);
    float rm = 1.0f, lgm = 0.0f, sigma = 0.0f;

    for (int t = 1;; ++t) {
        const int par = t & 1;

        // prefetch next step's f, mu (independent of everything below)
        int tn = (t < NT) ? t : (NT - 1);
        float f_nxt = __ldg(&fp[(size_t)tn * NC + c]);
        float mu_nxt = __ldg(&g_mu[b * NT + tn]);

        // window: fold 1/m_{t-1} and advance by F_{t-1}
        float fr = f_cur * rm;
#pragma unroll
        for (int j = MAXK - 1; j >= 1; --j) v[j] = v[j - 1] * fr;
        v[0] = wv * fr;
        float al0 = 0.f, al1 = 0.f, al2 = 0.f, al3 = 0.f;
#pragma unroll
        for (int j = 0; j < MAXK; j += 4) {
            al0 = fmaf(v[j], Dr[j], al0);
            al1 = fmaf(v[j + 1], Dr[j + 1], al1);
            al2 = fmaf(v[j + 2], Dr[j + 2], al2);
            al3 = fmaf(v[j + 3], Dr[j + 3], al3);
        }
        float al = (al0 + al1) + (al2 + al3);

        sigma += mu_cur + lgm;  // uniform across threads

        if (t == len) {
            float s = al;
#pragma unroll
            for (int o = 16; o >= 1; o >>= 1)
                s += __shfl_xor_sync(0xffffffffu, s, o);
            if (lane == 0) shs[w] = s;
            __syncthreads();
            if (c == 0) {
                float st = (shs[0] + shs[1]) + (shs[2] + shs[3]);
                out[b] = sigma + logf(st);
            }
            break;
        }

        // publish alpha, then barrier1
        psh[par][c] = al;
        __syncthreads();

        // warp max chain issues first (latency hidden under matvec)
        float mx = al;
#pragma unroll
        for (int o = 16; o >= 1; o >>= 1)
            mx = fmaxf(mx, __shfl_xor_sync(0xffffffffu, mx, o));
        if (lane == 0) shm[par][w] = mx;

        // full-row matvec on unnormalized alpha: wv = E[c,:] . al[:]
        const float* pb = &psh[par][0];
        ull acc0 = 0ull, acc1 = 0ull, acc2 = 0ull, acc3 = 0ull;
#pragma unroll
        for (int k = 0; k < 32; k += 2) {
            U2 p0, p1;
            p0.f4 = *(const float4*)&pb[k * 4];
            p1.f4 = *(const float4*)&pb[k * 4 + 4];
            FMA2(acc0, Er2[k * 2], p0.u[0]);
            FMA2(acc1, Er2[k * 2 + 1], p0.u[1]);
            FMA2(acc2, Er2[k * 2 + 2], p1.u[0]);
            FMA2(acc3, Er2[k * 2 + 3], p1.u[1]);
        }
        float x0, y0, x1, y1, x2, y2, x3, y3;
        UNPACK2(x0, y0, acc0); UNPACK2(x1, y1, acc1);
        UNPACK2(x2, y2, acc2); UNPACK2(x3, y3, acc3);
        wv = ((x0 + y0) + (x1 + y1)) + ((x2 + y2) + (x3 + y3));

        // barrier2: warp maxes visible; combine for next step's normalizer
        __syncthreads();
        float4 mv = *(const float4*)&shm[par][0];
        float m = fmaxf(fmaxf(mv.x, mv.y), fmaxf(mv.z, mv.w));
        rm = __fdividef(1.0f, m);
        lgm = __logf(m);

        f_cur = f_nxt;
        mu_cur = mu_nxt;
    }
}

extern "C" void kernel_launch(void* const* d_in, const int* in_sizes, int n_in,
                              void* d_out, int out_size) {
    const float* feat    = (const float*)d_in[0];
    const int*   lengths = (const int*)d_in[1];
    const float* means   = (const float*)d_in[2];
    const float* cov     = (const float*)d_in[3];
    const float* trans   = (const float*)d_in[4];
    const float* initlg  = (const float*)d_in[5];
    const float* lograte = (const float*)d_in[6];
    float* out = (float*)d_out;

    prep_kernel<<<NC + 1, 128>>>(means, cov, trans, initlg, lograte);
    emis_kernel<<<256, 256>>>(feat);
    rec_kernel<<<NB, 128>>>(lengths, out);
}

// round 7
// speedup vs baseline: 1.9844x; 1.1417x over previous
#include <cuda_runtime.h>
#include <cuda_bf16.h>
#include <math.h>
#include <stdint.h>

#define NB 16
#define NT 2048
#define ND 256
#define NC 128
#define MAXK 20

typedef unsigned long long ull;

union U2 { float4 f4; ull u[2]; };

#define FMA2(acc, a, b) asm("fma.rn.f32x2 %0, %1, %2, %0;" : "+l"(acc) : "l"(a), "l"(b))
#define PACK2(d, x, y)  asm("mov.b64 %0, {%1, %2};" : "=l"(d) : "f"(x), "f"(y))
#define UNPACK2(x, y, d) asm("mov.b64 {%0, %1}, %2;" : "=f"(x), "=f"(y) : "l"(d))

// ---------- device scratch ----------
__device__ float g_E[NC * NC];        // exp(trans_lp) row-major, diag 0
__device__ float g_winit[NC];         // exp(init_lp)
__device__ float g_dtab[MAXK * NC];   // exp(len_lp[l-1][c])
__device__ float g_miT[ND * NC];      // (means*inv_var)^T  [d][c]
__device__ float g_cb[NC];            // const - 0.5*mq[c]
__device__ float g_iv[ND];            // 1/cov
__device__ float g_f[(size_t)NB * NT * NC]; // exp(emis - rowmax)
__device__ float g_mu[NB * NT];       // rowmax(emis)

// ---------- prep: 129 blocks x 128 ----------
__global__ void prep_kernel(const float* __restrict__ means,
                            const float* __restrict__ cov,
                            const float* __restrict__ trans,
                            const float* __restrict__ initlg,
                            const float* __restrict__ lograte) {
    const int c = threadIdx.x;
    const int lane = c & 31, wid = c >> 5;

    if (blockIdx.x < NC) {
        const int col = blockIdx.x;
#pragma unroll
        for (int u = 0; u < 2; ++u) {
            int d = col + u * 128;
            float iv = __fdividef(1.0f, cov[d]);
            if (c == 0) g_iv[d] = iv;
            g_miT[d * NC + c] = means[c * ND + d] * iv;
        }
        // E column col: softmax over rows of masked logits
        __shared__ float red[4];
        float v = (c == col) ? -1.0e9f : trans[c * NC + col];
        float mx = v;
#pragma unroll
        for (int o = 16; o >= 1; o >>= 1)
            mx = fmaxf(mx, __shfl_xor_sync(0xffffffffu, mx, o));
        if (lane == 0) red[wid] = mx;
        __syncthreads();
        mx = fmaxf(fmaxf(red[0], red[1]), fmaxf(red[2], red[3]));
        __syncthreads();
        float ex = (c == col) ? 0.0f : __expf(v - mx);
        float s = ex;
#pragma unroll
        for (int o = 16; o >= 1; o >>= 1)
            s += __shfl_xor_sync(0xffffffffu, s, o);
        if (lane == 0) red[wid] = s;
        __syncthreads();
        float tot = red[0] + red[1] + red[2] + red[3];
        g_E[c * NC + col] = __fdividef(ex, tot);
        return;
    }

    // block NC: cb, winit, dtab
    __shared__ float red2[4];
    __shared__ float shc;

    float lsum = 0.f;
    for (int d = c; d < ND; d += NC) lsum += __logf(cov[d]);
#pragma unroll
    for (int o = 16; o >= 1; o >>= 1)
        lsum += __shfl_xor_sync(0xffffffffu, lsum, o);
    if (lane == 0) red2[wid] = lsum;
    __syncthreads();
    if (c == 0)
        shc = -0.5f * (256.0f * 1.8378770664093453f +
                       red2[0] + red2[1] + red2[2] + red2[3]);
    __syncthreads();
    const float cst = shc;

    float mq = 0.f;
#pragma unroll 8
    for (int d = 0; d < ND; ++d) {
        float m = means[c * ND + d];
        mq = fmaf(m * m, __fdividef(1.0f, cov[d]), mq);
    }
    g_cb[c] = cst - 0.5f * mq;

    // winit: parallel softmax
    {
        float il = initlg[c];
        float mx = il;
#pragma unroll
        for (int o = 16; o >= 1; o >>= 1)
            mx = fmaxf(mx, __shfl_xor_sync(0xffffffffu, mx, o));
        __syncthreads();
        if (lane == 0) red2[wid] = mx;
        __syncthreads();
        mx = fmaxf(fmaxf(red2[0], red2[1]), fmaxf(red2[2], red2[3]));
        float ex = __expf(il - mx);
        float s = ex;
#pragma unroll
        for (int o = 16; o >= 1; o >>= 1)
            s += __shfl_xor_sync(0xffffffffu, s, o);
        __syncthreads();
        if (lane == 0) red2[wid] = s;
        __syncthreads();
        float tot = red2[0] + red2[1] + red2[2] + red2[3];
        g_winit[c] = __fdividef(ex, tot);
    }

    float r = lograte[c];
    float lam = __expf(r);
    float lg = 0.f;
    for (int l = 1; l <= MAXK; ++l) {
        lg += __logf((float)l);
        g_dtab[(l - 1) * NC + c] = __expf(fmaf((float)l, r, -lam) - lg);
    }
}

// ---------- emission GEMM + exp epilogue: 256 blocks x 256 ----------
__global__ __launch_bounds__(256) void emis_kernel(const float* __restrict__ feat) {
    __shared__ float A[128][40];
    __shared__ float Bt[32][132];
    __shared__ float ivs[32];

    const int tid = threadIdx.x;
    const int r0 = blockIdx.x * 128;
    const int cg = tid & 15;
    const int rr = tid >> 4;

    ull acc2[8][4];
#pragma unroll
    for (int i = 0; i < 8; ++i)
#pragma unroll
        for (int k = 0; k < 4; ++k) acc2[i][k] = 0ull;
    float xq[8];
#pragma unroll
    for (int i = 0; i < 8; ++i) xq[i] = 0.f;

    for (int d0 = 0; d0 < ND; d0 += 32) {
        __syncthreads();
#pragma unroll
        for (int k = 0; k < 4; ++k) {
            int i = tid + k * 256;
            int row = i >> 3, q = i & 7;
            *(float4*)&A[row][q * 4] = *(const float4*)&feat[(size_t)(r0 + row) * ND + d0 + q * 4];
        }
#pragma unroll
        for (int k = 0; k < 4; ++k) {
            int i = tid + k * 256;
            int drow = i >> 5, q = i & 31;
            *(float4*)&Bt[drow][q * 4] = *(const float4*)&g_miT[(size_t)(d0 + drow) * NC + q * 4];
        }
        if (tid < 32) ivs[tid] = g_iv[d0 + tid];
        __syncthreads();

#pragma unroll
        for (int u = 0; u < 2; ++u) {
            int dd = cg + u * 16;
            float iv = ivs[dd];
#pragma unroll
            for (int i = 0; i < 8; ++i) {
                float a = A[rr + 16 * i][dd];
                xq[i] = fmaf(a * iv, a, xq[i]);
            }
        }

#pragma unroll 8
        for (int dd = 0; dd < 32; ++dd) {
            U2 b0, b1;
            b0.f4 = *(const float4*)&Bt[dd][cg * 4];
            b1.f4 = *(const float4*)&Bt[dd][64 + cg * 4];
#pragma unroll
            for (int i = 0; i < 8; ++i) {
                float a = A[rr + 16 * i][dd];
                ull aa;
                PACK2(aa, a, a);
                FMA2(acc2[i][0], aa, b0.u[0]);
                FMA2(acc2[i][1], aa, b0.u[1]);
                FMA2(acc2[i][2], aa, b1.u[0]);
                FMA2(acc2[i][3], aa, b1.u[1]);
            }
        }
    }

#pragma unroll
    for (int o = 1; o < 16; o <<= 1) {
#pragma unroll
        for (int i = 0; i < 8; ++i)
            xq[i] += __shfl_xor_sync(0xffffffffu, xq[i], o, 16);
    }

    float cb[8];
    {
        float4 cb0 = *(const float4*)&g_cb[cg * 4];
        float4 cb1 = *(const float4*)&g_cb[64 + cg * 4];
        cb[0] = cb0.x; cb[1] = cb0.y; cb[2] = cb0.z; cb[3] = cb0.w;
        cb[4] = cb1.x; cb[5] = cb1.y; cb[6] = cb1.z; cb[7] = cb1.w;
    }
    const float L2E = 1.4426950408889634f;

#pragma unroll
    for (int i = 0; i < 8; ++i) {
        float hq = -0.5f * xq[i];
        float e[8], m = -3.0e38f;
#pragma unroll
        for (int k = 0; k < 4; ++k) {
            float lo, hi;
            UNPACK2(lo, hi, acc2[i][k]);
            e[k * 2] = lo + hq + cb[k * 2];
            e[k * 2 + 1] = hi + hq + cb[k * 2 + 1];
        }
#pragma unroll
        for (int k = 0; k < 8; ++k) m = fmaxf(m, e[k]);
#pragma unroll
        for (int off = 8; off >= 1; off >>= 1)
            m = fmaxf(m, __shfl_xor_sync(0xffffffffu, m, off, 16));
        float4 o0, o1;
        o0.x = exp2f((e[0] - m) * L2E); o0.y = exp2f((e[1] - m) * L2E);
        o0.z = exp2f((e[2] - m) * L2E); o0.w = exp2f((e[3] - m) * L2E);
        o1.x = exp2f((e[4] - m) * L2E); o1.y = exp2f((e[5] - m) * L2E);
        o1.z = exp2f((e[6] - m) * L2E); o1.w = exp2f((e[7] - m) * L2E);
        size_t row = (size_t)(r0 + rr + 16 * i);
        *(float4*)&g_f[row * NC + cg * 4] = o0;
        *(float4*)&g_f[row * NC + 64 + cg * 4] = o1;
        if (cg == 0) g_mu[row] = m;
    }
}

// ---------- recursion: 16 blocks x 128, ONE barrier/step, fresh norm ----------
__global__ __launch_bounds__(128, 1) void rec_kernel(const int* __restrict__ lengths,
                                                     float* __restrict__ out) {
    const int b = blockIdx.x, c = threadIdx.x;
    const int w = c >> 5, lane = c & 31;
    __shared__ __align__(16) float psh[2][NC];
    __shared__ __align__(16) unsigned shu[2][4];
    __shared__ float shs[4];

    // full E row, packed pairs
    ull Er2[64];
#pragma unroll
    for (int k = 0; k < 32; ++k) {
        U2 u;
        u.f4 = *(const float4*)&g_E[c * NC + k * 4];
        Er2[k * 2] = u.u[0];
        Er2[k * 2 + 1] = u.u[1];
    }
    float Dr[MAXK];
#pragma unroll
    for (int j = 0; j < MAXK; ++j) Dr[j] = g_dtab[j * NC + c];
    float v[MAXK];
#pragma unroll
    for (int j = 0; j < MAXK; ++j) v[j] = 0.f;

    const int len = lengths[b];
    const float* fp = g_f + (size_t)b * NT * NC;
    float wv = g_winit[c];
    float f_cur = __ldg(&fp[c]);
    float mu_cur = __ldg(&g_mu[b * NT]);
    float rm = 1.0f;   // 2^-kcur, from max(al_{t-1}) : 1-step stale (stable)
    int kcur = 0;
    float sigma = 0.0f;
    int ks = 0;

    for (int t = 1;; ++t) {
        const int par = t & 1;

        // prefetch next step's f, mu
        int tn = (t < NT) ? t : (NT - 1);
        float f_nxt = __ldg(&fp[(size_t)tn * NC + c]);
        float mu_nxt = __ldg(&g_mu[b * NT + tn]);

        // alpha via dot on OLD window (short dependency cone):
        // al = fr * ( wv*D[0] + sum_{j=1..19} v[j-1]*D[j] )
        float fr = f_cur * rm;
        float d0 = wv * Dr[0];
        float d1 = 0.f, d2 = 0.f, d3 = 0.f;
#pragma unroll
        for (int j = 1; j < MAXK; j += 4) {
            d0 = fmaf(v[j - 1], Dr[j], d0);
            if (j + 1 < MAXK) d1 = fmaf(v[j], Dr[j + 1], d1);
            if (j + 2 < MAXK) d2 = fmaf(v[j + 1], Dr[j + 2], d2);
            if (j + 3 < MAXK) d3 = fmaf(v[j + 2], Dr[j + 3], d3);
        }
        float al = fr * ((d0 + d1) + (d2 + d3));

        sigma += mu_cur;   // uniform across threads
        ks += kcur;

        if (t == len) {
            float s = al;
#pragma unroll
            for (int o = 16; o >= 1; o >>= 1)
                s += __shfl_xor_sync(0xffffffffu, s, o);
            if (lane == 0) shs[w] = s;
            __syncthreads();
            if (c == 0) {
                float st = (shs[0] + shs[1]) + (shs[2] + shs[3]);
                out[b] = sigma + (float)ks * 0.6931471805599453f + logf(st);
            }
            break;
        }

        // warp max via single redux (u32 order == float order for al >= 0)
        unsigned mu32;
        asm("redux.sync.max.u32 %0, %1, 0xffffffff;"
            : "=r"(mu32) : "r"(__float_as_uint(al)));
        if (lane == 0) shu[par][w] = mu32;
        psh[par][c] = al;
        __syncthreads();

        // FRESH normalizer for step t+1 from max(al_t) (exponent only)
        unsigned m01 = shu[par][0] > shu[par][1] ? shu[par][0] : shu[par][1];
        unsigned m23 = shu[par][2] > shu[par][3] ? shu[par][2] : shu[par][3];
        unsigned mm = m01 > m23 ? m01 : m23;
        unsigned e = mm >> 23;
        rm = __uint_as_float((254u - e) << 23);     // 2^(127-e)
        kcur = (int)e - 127;

        // window update (uses same fr as al_t for consistency)
#pragma unroll
        for (int j = MAXK - 1; j >= 1; --j) v[j] = v[j - 1] * fr;
        v[0] = wv * fr;

        // full-row matvec on unnormalized alpha
        const float* pb = &psh[par][0];
        ull acc0 = 0ull, acc1 = 0ull, acc2 = 0ull, acc3 = 0ull;
#pragma unroll
        for (int k = 0; k < 32; k += 2) {
            U2 p0, p1;
            p0.f4 = *(const float4*)&pb[k * 4];
            p1.f4 = *(const float4*)&pb[k * 4 + 4];
            FMA2(acc0, Er2[k * 2], p0.u[0]);
            FMA2(acc1, Er2[k * 2 + 1], p0.u[1]);
            FMA2(acc2, Er2[k * 2 + 2], p1.u[0]);
            FMA2(acc3, Er2[k * 2 + 3], p1.u[1]);
        }
        float x0, y0, x1, y1, x2, y2, x3, y3;
        UNPACK2(x0, y0, acc0); UNPACK2(x1, y1, acc1);
        UNPACK2(x2, y2, acc2); UNPACK2(x3, y3, acc3);
        wv = ((x0 + y0) + (x1 + y1)) + ((x2 + y2) + (x3 + y3));

        f_cur = f_nxt;
        mu_cur = mu_nxt;
    }
}

extern "C" void kernel_launch(void* const* d_in, const int* in_sizes, int n_in,
                              void* d_out, int out_size) {
    const float* feat    = (const float*)d_in[0];
    const int*   lengths = (const int*)d_in[1];
    const float* means   = (const float*)d_in[2];
    const float* cov     = (const float*)d_in[3];
    const float* trans   = (const float*)d_in[4];
    const float* initlg  = (const float*)d_in[5];
    const float* lograte = (const float*)d_in[6];
    float* out = (float*)d_out;

    prep_kernel<<<NC + 1, 128>>>(means, cov, trans, initlg, lograte);
    emis_kernel<<<256, 256>>>(feat);
    rec_kernel<<<NB, 128>>>(lengths, out);
}